// round 1
// baseline (speedup 1.0000x reference)
#include <cuda_runtime.h>
#include <stdint.h>

#define H_IMG   1024
#define W_IMG   1024
#define R_TILE  64
#define HALO    5
#define SH_ROWS (R_TILE + 2 * HALO)   // 74
#define WORDS   (W_IMG / 32)          // 32 words of 32 bits per row
#define SH_W    (WORDS + 2)           // +2 guard columns (always 0)
#define THREADS 256

// spread 8 bits (b0..b7) to positions 0,4,8,...,28
__device__ __forceinline__ uint32_t spread4(uint32_t x) {
    x &= 0xFFu;
    x = (x | (x << 12)) & 0x000F000Fu;
    x = (x | (x << 6))  & 0x03030303u;
    x = (x | (x << 3))  & 0x11111111u;
    return x;
}

__global__ __launch_bounds__(THREADS)
void dilate_mask_kernel(const float* __restrict__ in, float* __restrict__ out) {
    __shared__ uint32_t buf[2][SH_ROWS][SH_W];

    const int tid    = threadIdx.x;
    const int lane   = tid & 31;
    const int warpId = tid >> 5;
    const int batch  = blockIdx.y;
    const int row0   = blockIdx.x * R_TILE;           // first output row of this tile

    const float* img  = in  + (size_t)batch * H_IMG * W_IMG;
    float*       oimg = out + (size_t)batch * H_IMG * W_IMG;

    // zero guard columns of both buffers (never written afterwards)
    for (int r = tid; r < SH_ROWS; r += THREADS) {
        buf[0][r][0] = 0u; buf[0][r][SH_W - 1] = 0u;
        buf[1][r][0] = 0u; buf[1][r][SH_W - 1] = 0u;
    }

    // ---- pack: coalesced float4 loads + 4 ballots + bit-interleave ----
    // Each warp step handles one 128-pixel segment of one row -> 4 words.
    for (int g = warpId; g < SH_ROWS * 8; g += THREADS / 32) {
        const int r   = g >> 3;
        const int seg = g & 7;                         // 128-px segment within row
        const int gr  = row0 - HALO + r;               // global image row
        uint32_t b0 = 0, b1 = 0, b2 = 0, b3 = 0;
        if (gr >= 0 && gr < H_IMG) {                   // warp-uniform branch
            const float4 v = reinterpret_cast<const float4*>(
                img + (size_t)gr * W_IMG + seg * 128)[lane];
            b0 = __ballot_sync(0xFFFFFFFFu, v.x != 0.0f);
            b1 = __ballot_sync(0xFFFFFFFFu, v.y != 0.0f);
            b2 = __ballot_sync(0xFFFFFFFFu, v.z != 0.0f);
            b3 = __ballot_sync(0xFFFFFFFFu, v.w != 0.0f);
        }
        if (lane < 4) {
            // word k (k = lane) covers pixels [seg*128 + 32k, +32): bit m comes
            // from b_{m&3} bit (8k + (m>>2))
            const int s = lane * 8;
            uint32_t w = spread4(b0 >> s)
                       | (spread4(b1 >> s) << 1)
                       | (spread4(b2 >> s) << 2)
                       | (spread4(b3 >> s) << 3);
            buf[0][r][1 + seg * 4 + lane] = w;
        }
    }
    __syncthreads();

    // ---- 5 iterations of 4-connected dilation on bit words ----
    int cur = 0;
    #pragma unroll
    for (int it = 0; it < 5; ++it) {
        const int nxt = cur ^ 1;
        for (int idx = tid; idx < SH_ROWS * WORDS; idx += THREADS) {
            const int r = idx >> 5;            // idx / WORDS
            const int w = (idx & 31) + 1;      // +1: skip guard column
            const uint32_t c  = buf[cur][r][w];
            const uint32_t lw = buf[cur][r][w - 1];
            const uint32_t rw = buf[cur][r][w + 1];
            const uint32_t up = (r > 0)           ? buf[cur][r - 1][w] : 0u;
            const uint32_t dn = (r < SH_ROWS - 1) ? buf[cur][r + 1][w] : 0u;
            // left/right pixel shifts with cross-word carry
            const uint32_t res = c | up | dn
                               | (c << 1) | (lw >> 31)
                               | (c >> 1) | (rw << 31);
            buf[nxt][r][w] = res;
        }
        __syncthreads();
        cur = nxt;
    }

    // ---- unpack: one float4 store per thread-step, fully coalesced ----
    for (int idx = tid; idx < R_TILE * (W_IMG / 4); idx += THREADS) {
        const int r  = idx >> 8;               // idx / 256
        const int x4 = idx & 255;
        const int x  = x4 * 4;
        const uint32_t word = buf[cur][r + HALO][1 + (x >> 5)];
        const int b = x & 31;
        float4 v;
        v.x = ((word >> (b + 0)) & 1u) ? 1.0f : 0.0f;
        v.y = ((word >> (b + 1)) & 1u) ? 1.0f : 0.0f;
        v.z = ((word >> (b + 2)) & 1u) ? 1.0f : 0.0f;
        v.w = ((word >> (b + 3)) & 1u) ? 1.0f : 0.0f;
        *reinterpret_cast<float4*>(oimg + (size_t)(row0 + r) * W_IMG + x) = v;
    }
}

extern "C" void kernel_launch(void* const* d_in, const int* in_sizes, int n_in,
                              void* d_out, int out_size) {
    const float* mask = (const float*)d_in[0];   // (16,1,1024,1024) f32
    // d_in[1] = weight (fixed Laplacian cross), d_in[2] = iter_num (=5): the
    // operation reduces exactly to 5 iterations of 4-connected binary dilation.
    float* out = (float*)d_out;

    dim3 grid(H_IMG / R_TILE, 16);   // 16 row-tiles x 16 batch images
    dilate_mask_kernel<<<grid, THREADS>>>(mask, out);
}

// round 2
// speedup vs baseline: 1.7813x; 1.7813x over previous
#include <cuda_runtime.h>
#include <stdint.h>

#define B_IMG   16
#define H_IMG   1024
#define W_IMG   1024
#define WORDS   32                   // 32-bit words per 1024-px row
#define R_STRIP 8                    // output rows per warp in kernel B
#define HALO    5
#define SROWS   (R_STRIP + 2 * HALO) // 18 rows held in registers

// 2 MB packed bitmap scratch — stays resident in L2 (126 MB) between kernels.
__device__ uint32_t g_packed[B_IMG * H_IMG * WORDS];

// spread 8 bits (b0..b7) to positions 0,4,8,...,28
__device__ __forceinline__ uint32_t spread4(uint32_t x) {
    x &= 0xFFu;
    x = (x | (x << 12)) & 0x000F000Fu;
    x = (x | (x << 6))  & 0x03030303u;
    x = (x | (x << 3))  & 0x11111111u;
    return x;
}

// ---------------------------------------------------------------------------
// Kernel A: pack 64 MB of {0,1} floats into a 2 MB bitmap.
// Each warp handles 1024 consecutive floats -> 32 words. Lane pre-loads 8
// independent float4s (MLP=8) before any ballot touches them.
// ---------------------------------------------------------------------------
__global__ __launch_bounds__(256)
void pack_kernel(const float* __restrict__ in) {
    const int lane = threadIdx.x & 31;
    const int wg   = (blockIdx.x * blockDim.x + threadIdx.x) >> 5; // 0..16383

    const float4* src = reinterpret_cast<const float4*>(in) + (size_t)wg * 256;
    float4 v[8];
#pragma unroll
    for (int i = 0; i < 8; ++i)
        v[i] = src[i * 32 + lane];          // coalesced, 8 loads in flight

    // pass i covers pixels [128i, 128i+128); lane j (j = 4i+k) will own word j
    uint32_t b0 = 0, b1 = 0, b2 = 0, b3 = 0;
#pragma unroll
    for (int i = 0; i < 8; ++i) {
        const uint32_t c0 = __ballot_sync(0xFFFFFFFFu, v[i].x != 0.0f);
        const uint32_t c1 = __ballot_sync(0xFFFFFFFFu, v[i].y != 0.0f);
        const uint32_t c2 = __ballot_sync(0xFFFFFFFFu, v[i].z != 0.0f);
        const uint32_t c3 = __ballot_sync(0xFFFFFFFFu, v[i].w != 0.0f);
        if ((lane >> 2) == i) { b0 = c0; b1 = c1; b2 = c2; b3 = c3; }
    }
    const int s = (lane & 3) * 8;
    const uint32_t w = spread4(b0 >> s)
                     | (spread4(b1 >> s) << 1)
                     | (spread4(b2 >> s) << 2)
                     | (spread4(b3 >> s) << 3);
    g_packed[(size_t)wg * 32 + lane] = w;    // coalesced 128B per warp
}

// ---------------------------------------------------------------------------
// Kernel B: per-warp register-resident dilation + unpack.
// Lane l holds word l (pixels [32l, 32l+32)) of each of 18 rows. 5 iterations
// of 4-connected dilation: vertical neighbors are registers, horizontal
// cross-word carries via shfl. Halo rows computed with 0-boundary cannot
// contaminate the 8 output rows within 5 iterations.
// ---------------------------------------------------------------------------
__global__ __launch_bounds__(256)
void dilate_unpack_kernel(float* __restrict__ out) {
    const int lane  = threadIdx.x & 31;
    const int wg    = (blockIdx.x * blockDim.x + threadIdx.x) >> 5; // 0..2047
    const int img   = wg >> 7;            // 128 strips per image
    const int strip = wg & 127;
    const int r0    = strip * R_STRIP;

    const uint32_t* pimg = g_packed + (size_t)img * H_IMG * WORDS;

    uint32_t m[SROWS];
#pragma unroll
    for (int r = 0; r < SROWS; ++r) {
        const int gr = r0 - HALO + r;
        m[r] = (gr >= 0 && gr < H_IMG) ? pimg[gr * WORDS + lane] : 0u;
    }

#pragma unroll 1
    for (int it = 0; it < 5; ++it) {
        uint32_t prev = 0u;                // old value of row r-1
#pragma unroll
        for (int r = 0; r < SROWS; ++r) {
            const uint32_t cur = m[r];
            const uint32_t dn  = (r < SROWS - 1) ? m[r + 1] : 0u;
            uint32_t lw = __shfl_up_sync(0xFFFFFFFFu, cur, 1);
            uint32_t rw = __shfl_down_sync(0xFFFFFFFFu, cur, 1);
            if (lane == 0)  lw = 0u;       // image edge: clamp == no-op for OR
            if (lane == 31) rw = 0u;
            m[r] = cur | prev | dn
                 | (cur << 1) | (lw >> 31)
                 | (cur >> 1) | (rw << 31);
            prev = cur;
        }
    }

    // unpack + coalesced float4 stores via shfl transpose
    float* obase = out + (size_t)img * H_IMG * W_IMG;
#pragma unroll
    for (int r = 0; r < R_STRIP; ++r) {
        const uint32_t word = m[HALO + r];
        float* orow = obase + (size_t)(r0 + r) * W_IMG;
#pragma unroll 1
        for (int p = 0; p < 8; ++p) {      // pass p: pixels [128p, 128p+128)
            const uint32_t w = __shfl_sync(0xFFFFFFFFu, word, 4 * p + (lane >> 3));
            const int b = (lane & 7) * 4;  // my 4 bits within that word
            float4 v;
            v.x = __uint_as_float((0u - ((w >> (b + 0)) & 1u)) & 0x3F800000u);
            v.y = __uint_as_float((0u - ((w >> (b + 1)) & 1u)) & 0x3F800000u);
            v.z = __uint_as_float((0u - ((w >> (b + 2)) & 1u)) & 0x3F800000u);
            v.w = __uint_as_float((0u - ((w >> (b + 3)) & 1u)) & 0x3F800000u);
            reinterpret_cast<float4*>(orow + p * 128)[lane] = v;
        }
    }
}

extern "C" void kernel_launch(void* const* d_in, const int* in_sizes, int n_in,
                              void* d_out, int out_size) {
    const float* mask = (const float*)d_in[0];   // (16,1,1024,1024) f32, binary
    // d_in[1] = fixed Laplacian-cross weight, d_in[2] = iter_num (=5):
    // the op reduces exactly to 5 iterations of 4-connected binary dilation.
    float* out = (float*)d_out;

    pack_kernel<<<2048, 256>>>(mask);            // 16384 warps, 1 chunk each
    dilate_unpack_kernel<<<256, 256>>>(out);     // 2048 warps, 1 strip each
}